// round 3
// baseline (speedup 1.0000x reference)
#include <cuda_runtime.h>
#include <cuda_bf16.h>
#include <math.h>

// ---------------- problem constants ----------------
#define BATCH     16
#define SEQLEN    4096
#define INPUT_DIM 57
#define D_MODEL   256
#define D_INNER   512
#define D_STATE   8
#define HEADDIM   16
#define NHEADS    32
#define CHUNKSZ   8
#define CONV_DIM  528          // D_INNER + 2*D_STATE
#define D_INPROJ  1072         // 2*D_INNER + 2*D_STATE + NHEADS
#define OUT_SIZE  6
#define NC        (SEQLEN/CHUNKSZ)   // 512 chunks per sequence
#define NSEG      16
#define CPS       (NC/NSEG)          // 32 chunks per segment
#define NTOK      (BATCH*SEQLEN)     // 65536

// ---------------- scratch (device globals; no allocations) ----------------
__device__ __align__(16) float g_Wc  [D_INPROJ*INPUT_DIM];
__device__ __align__(16) float g_bias[D_INPROJ];
__device__ __align__(16) float g_zx  [NTOK*D_INPROJ];      // in-proj output (z | xBC | dt)
__device__ __align__(16) float g_xbc [NTOK*CONV_DIM];      // conv+silu output
__device__ __align__(16) float g_Sfin[BATCH*NHEADS*NSEG*HEADDIM*D_STATE];
__device__ __align__(16) float g_Dseg[BATCH*NHEADS*NSEG];
__device__ __align__(16) float g_hin [BATCH*NHEADS*NSEG*HEADDIM*D_STATE];
__device__ __align__(16) float g_ybar[BATCH*D_INNER];

// ---------------- helpers ----------------
__device__ __forceinline__ float softplusf(float x) {
    return (x > 20.f) ? x : log1pf(expf(x));
}
__device__ __forceinline__ float siluf(float x) {
    return x / (1.f + expf(-x));
}
__device__ __forceinline__ unsigned long long f2pack(float lo, float hi) {
    unsigned long long r;
    asm("mov.b64 %0, {%1,%2};" : "=l"(r) : "f"(lo), "f"(hi));
    return r;
}
__device__ __forceinline__ void f2unpack(unsigned long long v, float& lo, float& hi) {
    asm("mov.b64 {%0,%1}, %2;" : "=f"(lo), "=f"(hi) : "l"(v));
}
__device__ __forceinline__ unsigned long long ffma2(unsigned long long a, unsigned long long b, unsigned long long c) {
    unsigned long long d;
    asm("fma.rn.f32x2 %0, %1, %2, %3;" : "=l"(d) : "l"(a), "l"(b), "l"(c));
    return d;
}

// ---------------- K1: W_comb = W_inproj @ W_in, bias = W_inproj @ b_in ----------------
__global__ void k_wcomb(const float* __restrict__ Wip, const float* __restrict__ Win,
                        const float* __restrict__ bin) {
    int idx = blockIdx.x * 256 + threadIdx.x;
    if (idx < D_INPROJ * INPUT_DIM) {
        int r = idx / INPUT_DIM, k = idx % INPUT_DIM;
        float s = 0.f;
        #pragma unroll 8
        for (int m = 0; m < D_MODEL; m++) s += Wip[r * D_MODEL + m] * Win[m * INPUT_DIM + k];
        g_Wc[idx] = s;
    } else if (idx < D_INPROJ * INPUT_DIM + D_INPROJ) {
        int r = idx - D_INPROJ * INPUT_DIM;
        float s = 0.f;
        #pragma unroll 8
        for (int m = 0; m < D_MODEL; m++) s += Wip[r * D_MODEL + m] * bin[m];
        g_bias[r] = s;
    }
}

// ---------------- K2: zxbcdt = x @ W_comb^T + bias  (M=65536, N=1072, K=57) ----------------
#define BM 128
#define BN 64
__global__ __launch_bounds__(256) void k_gemm(const float* __restrict__ x) {
    __shared__ __align__(16) float As[BM * INPUT_DIM];     // [row][k], row stride 57 (conflict-free w/ stride-16 row map)
    __shared__ __align__(16) float Bs[INPUT_DIM][BN];      // k-major
    const int tid = threadIdx.x;
    const int tx = tid & 15, ty = tid >> 4;
    const int m0 = blockIdx.x * BM;
    const int n0 = blockIdx.y * BN;

    for (int idx = tid; idx < BM * INPUT_DIM; idx += 256)
        As[idx] = x[(size_t)(m0 + idx / INPUT_DIM) * INPUT_DIM + idx % INPUT_DIM];
    for (int idx = tid; idx < BN * INPUT_DIM; idx += 256) {
        int c = idx / INPUT_DIM, k = idx % INPUT_DIM;
        int col = n0 + c;
        Bs[k][c] = (col < D_INPROJ) ? g_Wc[col * INPUT_DIM + k] : 0.f;
    }
    __syncthreads();

    unsigned long long acc[8][2];
    #pragma unroll
    for (int i = 0; i < 8; i++) { acc[i][0] = 0ull; acc[i][1] = 0ull; }

    #pragma unroll 3
    for (int k = 0; k < INPUT_DIM; k++) {
        float2 b01 = *reinterpret_cast<const float2*>(&Bs[k][tx * 4]);
        float2 b23 = *reinterpret_cast<const float2*>(&Bs[k][tx * 4 + 2]);
        unsigned long long b01p = f2pack(b01.x, b01.y);
        unsigned long long b23p = f2pack(b23.x, b23.y);
        #pragma unroll
        for (int i = 0; i < 8; i++) {
            float a = As[(ty + 16 * i) * INPUT_DIM + k];
            unsigned long long a2 = f2pack(a, a);
            acc[i][0] = ffma2(a2, b01p, acc[i][0]);
            acc[i][1] = ffma2(a2, b23p, acc[i][1]);
        }
    }

    const int col = n0 + tx * 4;
    if (col < D_INPROJ) {
        float bb0 = g_bias[col], bb1 = g_bias[col + 1], bb2 = g_bias[col + 2], bb3 = g_bias[col + 3];
        #pragma unroll
        for (int i = 0; i < 8; i++) {
            int row = m0 + ty + 16 * i;
            float r0, r1, r2, r3;
            f2unpack(acc[i][0], r0, r1);
            f2unpack(acc[i][1], r2, r3);
            float4 v = make_float4(r0 + bb0, r1 + bb1, r2 + bb2, r3 + bb3);
            *reinterpret_cast<float4*>(&g_zx[(size_t)row * D_INPROJ + col]) = v;
        }
    }
}

// ---------------- K3: causal depthwise conv (width 4) + silu on xBC slice ----------------
__global__ void k_conv(const float* __restrict__ cw, const float* __restrict__ cb) {
    const int ch = threadIdx.x;                 // 0..527
    const int blk = blockIdx.x;                 // b*(L/8) + t0/8
    const int b = blk >> 9;                     // L/8 = 512
    const int t0 = (blk & 511) * 8;
    const float w0 = cw[ch * 4 + 0], w1 = cw[ch * 4 + 1], w2 = cw[ch * 4 + 2], w3 = cw[ch * 4 + 3];
    const float bias = cb[ch];
    float v[11];
    #pragma unroll
    for (int tt = 0; tt < 11; tt++) {
        int t = t0 + tt - 3;
        v[tt] = (t >= 0) ? g_zx[(size_t)(b * SEQLEN + t) * D_INPROJ + D_INNER + ch] : 0.f;
    }
    #pragma unroll
    for (int u = 0; u < 8; u++) {
        float c = bias + w0 * v[u] + w1 * v[u + 1] + w2 * v[u + 2] + w3 * v[u + 3];
        g_xbc[(size_t)(b * SEQLEN + t0 + u) * CONV_DIM + ch] = siluf(c);
    }
}

// ---------------- K4: phase 1 — segment-local final state + decay product ----------------
__global__ __launch_bounds__(128) void k_phase1(const float* __restrict__ dtb, const float* __restrict__ Alog) {
    __shared__ float s_xh[4][CHUNKSZ][HEADDIM];
    __shared__ float s_B [4][CHUNKSZ][9];
    __shared__ float s_dtc[4][CHUNKSZ], s_cA[4][CHUNKSZ], s_coef[4][CHUNKSZ], s_cdec[4];
    const int w = threadIdx.x >> 5, lane = threadIdx.x & 31;
    const int gw = blockIdx.x * 4 + w;                // 0 .. 16*32*15-1
    const int b   = gw / (NHEADS * (NSEG - 1));
    const int rem = gw % (NHEADS * (NSEG - 1));
    const int h   = rem / (NSEG - 1);
    const int seg = rem % (NSEG - 1);
    const float A = -expf(Alog[h]);
    const float dtbias = dtb[h];
    const int p = lane >> 1, n0 = (lane & 1) * 4;
    const size_t rowbase = (size_t)b * SEQLEN;
    float hst[4] = {0.f, 0.f, 0.f, 0.f};
    float dec_total = 1.f;

    for (int c = seg * CPS; c < seg * CPS + CPS; c++) {
        const int t0 = c * CHUNKSZ;
        if (lane < 8) {
            float dtr = g_zx[(rowbase + t0 + lane) * D_INPROJ + (D_INNER + CONV_DIM) + h];
            s_dtc[w][lane] = softplusf(dtr + dtbias);
        }
        __syncwarp();
        if (lane < 8) {
            float cs = 0.f;
            for (int k = 0; k <= lane; k++) cs += s_dtc[w][k];
            s_cA[w][lane] = cs * A;
        }
        __syncwarp();
        if (lane < 8) {
            s_coef[w][lane] = expf(s_cA[w][7] - s_cA[w][lane]) * s_dtc[w][lane];
            if (lane == 0) s_cdec[w] = expf(s_cA[w][7]);
        }
        for (int e = lane; e < 128; e += 32) {
            int j = e >> 4, pp = e & 15;
            s_xh[w][j][pp] = g_xbc[(rowbase + t0 + j) * CONV_DIM + h * HEADDIM + pp];
        }
        for (int e = lane; e < 64; e += 32) {
            int j = e >> 3, n = e & 7;
            s_B[w][j][n] = g_xbc[(rowbase + t0 + j) * CONV_DIM + D_INNER + n];
        }
        __syncwarp();
        const float cdec = s_cdec[w];
        #pragma unroll
        for (int v = 0; v < 4; v++) {
            int n = n0 + v;
            float S = 0.f;
            #pragma unroll
            for (int j = 0; j < 8; j++) S += s_coef[w][j] * s_B[w][j][n] * s_xh[w][j][p];
            hst[v] = hst[v] * cdec + S;
        }
        dec_total *= cdec;
        __syncwarp();
    }
    size_t outb = (size_t)((b * NHEADS + h) * NSEG + seg) * 128;
    *reinterpret_cast<float4*>(&g_Sfin[outb + lane * 4]) = make_float4(hst[0], hst[1], hst[2], hst[3]);
    if (lane == 0) g_Dseg[(b * NHEADS + h) * NSEG + seg] = dec_total;
}

// ---------------- K5: phase 2 — combine segment states (linear scan over 16 segs) ----------------
__global__ void k_combine() {
    int tid = blockIdx.x * 128 + threadIdx.x;   // 65536 threads
    int bh = tid >> 7, pn = tid & 127;
    float H = 0.f;
    #pragma unroll
    for (int s = 0; s < NSEG; s++) {
        g_hin[(size_t)(bh * NSEG + s) * 128 + pn] = H;
        if (s < NSEG - 1)
            H = H * g_Dseg[bh * NSEG + s] + g_Sfin[(size_t)(bh * NSEG + s) * 128 + pn];
    }
}

// ---------------- K6: zero ybar accumulator ----------------
__global__ void k_zero() { g_ybar[blockIdx.x * D_INNER + threadIdx.x] = 0.f; }

// ---------------- K7: phase 3 — full chunk pass with correct h_in; gated mean accumulation ----------------
__global__ __launch_bounds__(128) void k_phase3(const float* __restrict__ dtb, const float* __restrict__ Alog,
                                                const float* __restrict__ Dp) {
    __shared__ float s_xh[4][8][16];
    __shared__ float s_z [4][8][16];
    __shared__ float s_B [4][8][9];
    __shared__ float s_C [4][8][9];
    __shared__ float s_sc[4][8][9];
    __shared__ float s_h [4][16][9];
    __shared__ float s_dtc[4][8], s_cA[4][8], s_coef[4][8], s_cdec[4];
    const int w = threadIdx.x >> 5, lane = threadIdx.x & 31;
    const int gw = blockIdx.x * 4 + w;              // 0..8191
    const int b   = gw >> 9;
    const int h   = (gw >> 4) & 31;
    const int seg = gw & 15;
    const float A = -expf(Alog[h]);
    const float dtbias = dtb[h];
    const float Dh = Dp[h];
    const size_t rowbase = (size_t)b * SEQLEN;

    {   // init state from h_in
        size_t hb = (size_t)((b * NHEADS + h) * NSEG + seg) * 128 + lane * 4;
        float4 hv = *reinterpret_cast<const float4*>(&g_hin[hb]);
        int p = lane >> 1, n0 = (lane & 1) * 4;
        s_h[w][p][n0 + 0] = hv.x; s_h[w][p][n0 + 1] = hv.y;
        s_h[w][p][n0 + 2] = hv.z; s_h[w][p][n0 + 3] = hv.w;
    }
    __syncwarp();

    const int i_ = lane >> 2, q = lane & 3;         // output map: lane -> (i, p=4q..4q+3)
    const int pS = lane >> 1, n0S = (lane & 1) * 4; // state map:  lane -> (p, n quad)
    float acc[4] = {0.f, 0.f, 0.f, 0.f};

    for (int c = seg * CPS; c < seg * CPS + CPS; c++) {
        const int t0 = c * CHUNKSZ;
        if (lane < 8) {
            float dtr = g_zx[(rowbase + t0 + lane) * D_INPROJ + (D_INNER + CONV_DIM) + h];
            s_dtc[w][lane] = softplusf(dtr + dtbias);
        }
        __syncwarp();
        if (lane < 8) {
            float cs = 0.f;
            for (int k = 0; k <= lane; k++) cs += s_dtc[w][k];
            s_cA[w][lane] = cs * A;
        }
        __syncwarp();
        if (lane < 8) {
            s_coef[w][lane] = expf(s_cA[w][7] - s_cA[w][lane]) * s_dtc[w][lane];
            if (lane == 0) s_cdec[w] = expf(s_cA[w][7]);
        }
        for (int e = lane; e < 128; e += 32) {
            int j = e >> 4, pp = e & 15;
            s_xh[w][j][pp] = g_xbc[(rowbase + t0 + j) * CONV_DIM + h * HEADDIM + pp];
            s_z [w][j][pp] = g_zx [(rowbase + t0 + j) * D_INPROJ + h * HEADDIM + pp];
        }
        for (int e = lane; e < 64; e += 32) {
            int j = e >> 3, n = e & 7;
            size_t r = (rowbase + t0 + j) * CONV_DIM;
            s_B[w][j][n] = g_xbc[r + D_INNER + n];
            s_C[w][j][n] = g_xbc[r + D_INNER + D_STATE + n];
        }
        __syncwarp();

        // scores[i][j] = (C_i . B_j) * exp(cA_i - cA_j) * dtc_j  (j<=i)
        for (int e = lane; e < 64; e += 32) {
            int si = e >> 3, sj = e & 7;
            float sc = 0.f;
            if (sj <= si) {
                float cb = 0.f;
                #pragma unroll
                for (int n = 0; n < 8; n++) cb += s_C[w][si][n] * s_B[w][sj][n];
                sc = cb * expf(s_cA[w][si] - s_cA[w][sj]) * s_dtc[w][sj];
            }
            s_sc[w][si][sj] = sc;
        }
        __syncwarp();

        // y[i][p] = y_intra + y_inter + D*xh, gated by silu(z), accumulated for mean
        const float eA = expf(s_cA[w][i_]);
        #pragma unroll
        for (int v = 0; v < 4; v++) {
            int p = q * 4 + v;
            float inter = 0.f;
            #pragma unroll
            for (int n = 0; n < 8; n++) inter += s_h[w][p][n] * s_C[w][i_][n];
            float y = eA * inter + Dh * s_xh[w][i_][p];
            #pragma unroll
            for (int j = 0; j < 8; j++) y += s_sc[w][i_][j] * s_xh[w][j][p];
            float zz = s_z[w][i_][p];
            acc[v] += y * siluf(zz);
        }
        __syncwarp();   // all reads of s_h done before update

        // state update: h = h*dec + S
        const float cdec = s_cdec[w];
        #pragma unroll
        for (int v = 0; v < 4; v++) {
            int n = n0S + v;
            float S = 0.f;
            #pragma unroll
            for (int j = 0; j < 8; j++) S += s_coef[w][j] * s_B[w][j][n] * s_xh[w][j][pS];
            s_h[w][pS][n] = s_h[w][pS][n] * cdec + S;
        }
        __syncwarp();
    }

    // reduce acc over the 8 i-lanes sharing each p-group (lanes stride 4)
    #pragma unroll
    for (int v = 0; v < 4; v++) {
        acc[v] += __shfl_down_sync(0xffffffffu, acc[v], 16);
        acc[v] += __shfl_down_sync(0xffffffffu, acc[v], 8);
        acc[v] += __shfl_down_sync(0xffffffffu, acc[v], 4);
    }
    if (lane < 4) {
        #pragma unroll
        for (int v = 0; v < 4; v++)
            atomicAdd(&g_ybar[b * D_INNER + h * HEADDIM + lane * 4 + v], acc[v]);
    }
}

// ---------------- K8: pooled = (ybar/L) @ W_out^T; logits = pooled @ W_cls^T + b_cls ----------------
__global__ void k_final(const float* __restrict__ Wout, const float* __restrict__ Wcls,
                        const float* __restrict__ bcls, float* __restrict__ out) {
    __shared__ float sp[D_MODEL];
    const int b = blockIdx.x, m = threadIdx.x;
    float s = 0.f;
    #pragma unroll 8
    for (int d = 0; d < D_INNER; d++) s += g_ybar[b * D_INNER + d] * Wout[m * D_INNER + d];
    sp[m] = s * (1.f / SEQLEN);
    __syncthreads();
    if (m < OUT_SIZE) {
        float r = bcls[m];
        #pragma unroll 8
        for (int k = 0; k < D_MODEL; k++) r += Wcls[m * D_MODEL + k] * sp[k];
        out[b * OUT_SIZE + m] = r;
    }
}

// ---------------- launch ----------------
extern "C" void kernel_launch(void* const* d_in, const int* in_sizes, int n_in,
                              void* d_out, int out_size) {
    const float* x    = (const float*)d_in[0];
    const float* Win  = (const float*)d_in[1];
    const float* bin  = (const float*)d_in[2];
    const float* Wip  = (const float*)d_in[3];
    const float* cw   = (const float*)d_in[4];
    const float* cb   = (const float*)d_in[5];
    const float* dtb  = (const float*)d_in[6];
    const float* Alog = (const float*)d_in[7];
    const float* Dp   = (const float*)d_in[8];
    const float* Wout = (const float*)d_in[9];
    const float* Wcls = (const float*)d_in[10];
    const float* bcls = (const float*)d_in[11];
    float* out = (float*)d_out;

    k_wcomb<<<243, 256>>>(Wip, Win, bin);
    dim3 g2(NTOK / BM, (D_INPROJ + BN - 1) / BN);        // 512 x 17
    k_gemm<<<g2, 256>>>(x);
    k_conv<<<BATCH * (SEQLEN / 8), CONV_DIM>>>(cw, cb);
    k_phase1<<<(BATCH * NHEADS * (NSEG - 1)) / 4, 128>>>(dtb, Alog);
    k_combine<<<512, 128>>>();
    k_zero<<<BATCH, D_INNER>>>();
    k_phase3<<<(BATCH * NHEADS * NSEG) / 4, 128>>>(dtb, Alog, Dp);
    k_final<<<BATCH, D_MODEL>>>(Wout, Wcls, bcls, out);
}

// round 5
// speedup vs baseline: 1.4506x; 1.4506x over previous
#include <cuda_runtime.h>
#include <cuda_bf16.h>
#include <math.h>

// ---------------- problem constants ----------------
#define BATCH     16
#define SEQLEN    4096
#define INPUT_DIM 57
#define D_MODEL   256
#define D_INNER   512
#define D_STATE   8
#define HEADDIM   16
#define NHEADS    32
#define CHUNKSZ   8
#define CONV_DIM  528          // D_INNER + 2*D_STATE
#define D_INPROJ  1072         // 2*D_INNER + 2*D_STATE + NHEADS
#define OUT_SIZE  6
#define NC        (SEQLEN/CHUNKSZ)   // 512 chunks per sequence
#define NSEG      16
#define CPS       (NC/NSEG)          // 32 chunks per segment
#define NTOK      (BATCH*SEQLEN)     // 65536

// ---------------- scratch (device globals; no allocations) ----------------
__device__ __align__(16) float g_Wc  [D_INPROJ*INPUT_DIM];
__device__ __align__(16) float g_bias[D_INPROJ];
__device__ __align__(16) float g_zx  [NTOK*D_INPROJ];      // in-proj output (z | xBC | dt)
__device__ __align__(16) __nv_bfloat16 g_S[(size_t)BATCH*NHEADS*NC*128]; // chunk state contribs
__device__ __align__(16) __nv_bfloat16 g_G[(size_t)BATCH*NHEADS*NC*128]; // chunk gated-C matrices
__device__ __align__(16) float g_d   [BATCH*NHEADS*NC];                  // chunk decays
__device__ __align__(16) float g_Sfin[BATCH*NHEADS*NSEG*HEADDIM*D_STATE];
__device__ __align__(16) float g_Dseg[BATCH*NHEADS*NSEG];
__device__ __align__(16) float g_hin [BATCH*NHEADS*NSEG*HEADDIM*D_STATE];
__device__ __align__(16) float g_ybar[BATCH*D_INNER];

// ---------------- helpers ----------------
__device__ __forceinline__ float siluf_fast(float x) {
    return x * __frcp_rn(1.f + __expf(-x));
}
__device__ __forceinline__ unsigned long long f2pack(float lo, float hi) {
    unsigned long long r;
    asm("mov.b64 %0, {%1,%2};" : "=l"(r) : "f"(lo), "f"(hi));
    return r;
}
__device__ __forceinline__ void f2unpack(unsigned long long v, float& lo, float& hi) {
    asm("mov.b64 {%0,%1}, %2;" : "=f"(lo), "=f"(hi) : "l"(v));
}
__device__ __forceinline__ unsigned long long ffma2(unsigned long long a, unsigned long long b, unsigned long long c) {
    unsigned long long d;
    asm("fma.rn.f32x2 %0, %1, %2, %3;" : "=l"(d) : "l"(a), "l"(b), "l"(c));
    return d;
}
__device__ __forceinline__ unsigned short bf_enc(float x) {
    return __bfloat16_as_ushort(__float2bfloat16_rn(x));
}
__device__ __forceinline__ float bf_dec(unsigned short u) {
    return __bfloat162float(__ushort_as_bfloat16(u));
}

// ---------------- K1: W_comb = W_inproj @ W_in, bias = W_inproj @ b_in ----------------
__global__ void k_wcomb(const float* __restrict__ Wip, const float* __restrict__ Win,
                        const float* __restrict__ bin) {
    int idx = blockIdx.x * 256 + threadIdx.x;
    if (idx < D_INPROJ * INPUT_DIM) {
        int r = idx / INPUT_DIM, k = idx % INPUT_DIM;
        float s = 0.f;
        #pragma unroll 8
        for (int m = 0; m < D_MODEL; m++) s += Wip[r * D_MODEL + m] * Win[m * INPUT_DIM + k];
        g_Wc[idx] = s;
    } else if (idx < D_INPROJ * INPUT_DIM + D_INPROJ) {
        int r = idx - D_INPROJ * INPUT_DIM;
        float s = 0.f;
        #pragma unroll 8
        for (int m = 0; m < D_MODEL; m++) s += Wip[r * D_MODEL + m] * bin[m];
        g_bias[r] = s;
    }
}

// ---------------- K2: zxbcdt = x @ W_comb^T + bias  (M=65536, N=1072, K=57) ----------------
#define BM 128
#define BN 64
__global__ __launch_bounds__(256) void k_gemm(const float* __restrict__ x) {
    __shared__ __align__(16) float As[BM * INPUT_DIM];
    __shared__ __align__(16) float Bs[INPUT_DIM][BN];
    const int tid = threadIdx.x;
    const int tx = tid & 15, ty = tid >> 4;
    const int m0 = blockIdx.x * BM;
    const int n0 = blockIdx.y * BN;

    for (int idx = tid; idx < BM * INPUT_DIM; idx += 256)
        As[idx] = x[(size_t)(m0 + idx / INPUT_DIM) * INPUT_DIM + idx % INPUT_DIM];
    for (int idx = tid; idx < BN * INPUT_DIM; idx += 256) {
        int c = idx / INPUT_DIM, k = idx % INPUT_DIM;
        int col = n0 + c;
        Bs[k][c] = (col < D_INPROJ) ? g_Wc[col * INPUT_DIM + k] : 0.f;
    }
    __syncthreads();

    unsigned long long acc[8][2];
    #pragma unroll
    for (int i = 0; i < 8; i++) { acc[i][0] = 0ull; acc[i][1] = 0ull; }

    #pragma unroll 3
    for (int k = 0; k < INPUT_DIM; k++) {
        float2 b01 = *reinterpret_cast<const float2*>(&Bs[k][tx * 4]);
        float2 b23 = *reinterpret_cast<const float2*>(&Bs[k][tx * 4 + 2]);
        unsigned long long b01p = f2pack(b01.x, b01.y);
        unsigned long long b23p = f2pack(b23.x, b23.y);
        #pragma unroll
        for (int i = 0; i < 8; i++) {
            float a = As[(ty + 16 * i) * INPUT_DIM + k];
            unsigned long long a2 = f2pack(a, a);
            acc[i][0] = ffma2(a2, b01p, acc[i][0]);
            acc[i][1] = ffma2(a2, b23p, acc[i][1]);
        }
    }

    const int col = n0 + tx * 4;
    if (col < D_INPROJ) {
        float bb0 = g_bias[col], bb1 = g_bias[col + 1], bb2 = g_bias[col + 2], bb3 = g_bias[col + 3];
        #pragma unroll
        for (int i = 0; i < 8; i++) {
            int row = m0 + ty + 16 * i;
            float r0, r1, r2, r3;
            f2unpack(acc[i][0], r0, r1);
            f2unpack(acc[i][1], r2, r3);
            float4 v = make_float4(r0 + bb0, r1 + bb1, r2 + bb2, r3 + bb3);
            *reinterpret_cast<float4*>(&g_zx[(size_t)row * D_INPROJ + col]) = v;
        }
    }
}

// ---------------- K3: zero ybar accumulator ----------------
__global__ void k_zero() { g_ybar[blockIdx.x * D_INNER + threadIdx.x] = 0.f; }

// ---------------- K4: pass A — per-chunk: conv+silu, intra-gated output, S/G/d summaries ----------------
#define CONVP 532   // padded row stride for conv smem (mult of 4 for float4, 532%32=20 -> conflict-free rows)
__global__ __launch_bounds__(256) void k_passA(const float* __restrict__ cw, const float* __restrict__ cb,
                                               const float* __restrict__ dtb, const float* __restrict__ Alog,
                                               const float* __restrict__ Dp) {
    __shared__ __align__(16) float s_conv[8 * CONVP];   // conv+silu output: [token][channel]
    __shared__ float s_dt[8][33];                       // raw dt: [token][head]
    __shared__ float s_CB[64];                          // C_i . B_j (head-independent)
    __shared__ float s_sz[8][8][20];                    // silu(z): [warp][token][p]

    const int tid = threadIdx.x, w = tid >> 5, lane = tid & 31;
    const int blk = blockIdx.x;
    const int b = blk >> 9, c = blk & 511;
    const int t0 = c * CHUNKSZ;
    const size_t base = (size_t)(b * SEQLEN + t0) * D_INPROJ;

    // dt tile (coalesced): 8 tokens x 32 heads
    {
        int j = tid >> 5, hh2 = tid & 31;
        s_dt[j][hh2] = g_zx[base + (size_t)j * D_INPROJ + (D_INNER + CONV_DIM) + hh2];
    }

    // depthwise causal conv (width 4) + silu into smem
    for (int ch = tid; ch < CONV_DIM; ch += 256) {
        const float w0 = cw[ch * 4], w1 = cw[ch * 4 + 1], w2 = cw[ch * 4 + 2], w3 = cw[ch * 4 + 3];
        const float bb = cb[ch];
        float v[11];
        #pragma unroll
        for (int tt = 0; tt < 11; tt++) {
            int t = t0 + tt - 3;
            v[tt] = (t >= 0) ? g_zx[(size_t)(b * SEQLEN + t) * D_INPROJ + D_INNER + ch] : 0.f;
        }
        #pragma unroll
        for (int u = 0; u < 8; u++) {
            float s = bb + w0 * v[u] + w1 * v[u + 1] + w2 * v[u + 2] + w3 * v[u + 3];
            s_conv[u * CONVP + ch] = siluf_fast(s);
        }
    }
    __syncthreads();

    // CB[i][j] = C_i . B_j  (shared across all 32 heads)
    if (tid < 64) {
        int i = tid >> 3, j = tid & 7;
        float s = 0.f;
        #pragma unroll
        for (int n = 0; n < 8; n++)
            s += s_conv[i * CONVP + 520 + n] * s_conv[j * CONVP + 512 + n];
        s_CB[tid] = s;
    }
    __syncthreads();

    #pragma unroll 1
    for (int hh = 0; hh < 4; hh++) {
        const int h = w * 4 + hh;
        const float A = -__expf(Alog[h]);
        const float Dh = Dp[h];

        // dtc + cumulative A on lanes 0..7, broadcast to register arrays
        float dtc_l = 0.f;
        if (lane < 8) {
            float xv = s_dt[lane][h] + dtb[h];
            dtc_l = (xv > 20.f) ? xv : __logf(1.f + __expf(xv));
        }
        float cs = dtc_l;
        #pragma unroll
        for (int off = 1; off < 8; off <<= 1) {
            float vv = __shfl_up_sync(0xffffffffu, cs, off);
            if (lane >= off) cs += vv;
        }
        float cA_l = cs * A;
        float dtc[8], cA[8];
        #pragma unroll
        for (int j = 0; j < 8; j++) {
            dtc[j] = __shfl_sync(0xffffffffu, dtc_l, j);
            cA[j]  = __shfl_sync(0xffffffffu, cA_l, j);
        }

        // ---- part 1: lane -> (i = lane>>2, q = lane&3); intra + D term, gated ----
        const int i_ = lane >> 2, q = lane & 3;
        float sc[8];
        #pragma unroll
        for (int j = 0; j < 8; j++)
            sc[j] = (j <= i_) ? s_CB[i_ * 8 + j] * __expf(cA[i_] - cA[j]) * dtc[j] : 0.f;

        float4 zq = *reinterpret_cast<const float4*>(&g_zx[base + (size_t)i_ * D_INPROJ + h * 16 + q * 4]);
        float sz0 = siluf_fast(zq.x), sz1 = siluf_fast(zq.y), sz2 = siluf_fast(zq.z), sz3 = siluf_fast(zq.w);
        s_sz[w][i_][q * 4 + 0] = sz0; s_sz[w][i_][q * 4 + 1] = sz1;
        s_sz[w][i_][q * 4 + 2] = sz2; s_sz[w][i_][q * 4 + 3] = sz3;

        float a0, a1, a2, a3;
        {
            const float* xr = &s_conv[h * 16 + q * 4];
            float4 xi = *reinterpret_cast<const float4*>(&xr[i_ * CONVP]);
            a0 = Dh * xi.x; a1 = Dh * xi.y; a2 = Dh * xi.z; a3 = Dh * xi.w;
            #pragma unroll
            for (int j = 0; j < 8; j++) {
                float4 xj = *reinterpret_cast<const float4*>(&xr[j * CONVP]);
                float s = sc[j];
                a0 += s * xj.x; a1 += s * xj.y; a2 += s * xj.z; a3 += s * xj.w;
            }
        }
        a0 *= sz0; a1 *= sz1; a2 *= sz2; a3 *= sz3;
        __syncwarp();

        // ---- part 2: lane -> (p = lane>>1, n0 = (lane&1)*4); S and G summaries ----
        const int p = lane >> 1, n0 = (lane & 1) * 4;
        float coef[8], e[8];
        #pragma unroll
        for (int j = 0; j < 8; j++) coef[j] = __expf(cA[7] - cA[j]) * dtc[j];
        #pragma unroll
        for (int j = 0; j < 8; j++) e[j] = __expf(cA[j]);

        float S0 = 0.f, S1 = 0.f, S2 = 0.f, S3 = 0.f;
        float G0 = 0.f, G1 = 0.f, G2 = 0.f, G3 = 0.f;
        #pragma unroll
        for (int k = 0; k < 8; k++) {
            float  xk  = s_conv[k * CONVP + h * 16 + p];
            float  szk = s_sz[w][k][p];
            float4 Bq  = *reinterpret_cast<const float4*>(&s_conv[k * CONVP + 512 + n0]);
            float4 Cq  = *reinterpret_cast<const float4*>(&s_conv[k * CONVP + 520 + n0]);
            float cx = coef[k] * xk;
            float es = e[k] * szk;
            S0 += cx * Bq.x; S1 += cx * Bq.y; S2 += cx * Bq.z; S3 += cx * Bq.w;
            G0 += es * Cq.x; G1 += es * Cq.y; G2 += es * Cq.z; G3 += es * Cq.w;
        }
        {
            size_t off = (size_t)((b * NHEADS + h) * NC + c) * 128 + lane * 4;
            ushort4 us; us.x = bf_enc(S0); us.y = bf_enc(S1); us.z = bf_enc(S2); us.w = bf_enc(S3);
            *reinterpret_cast<ushort4*>(&g_S[off]) = us;
            ushort4 ug; ug.x = bf_enc(G0); ug.y = bf_enc(G1); ug.z = bf_enc(G2); ug.w = bf_enc(G3);
            *reinterpret_cast<ushort4*>(&g_G[off]) = ug;
            if (lane == 0) g_d[(b * NHEADS + h) * NC + c] = __expf(cA[7]);
        }

        // reduce intra contribution over i-groups and accumulate
        #pragma unroll
        for (int off = 16; off >= 4; off >>= 1) {
            a0 += __shfl_down_sync(0xffffffffu, a0, off);
            a1 += __shfl_down_sync(0xffffffffu, a1, off);
            a2 += __shfl_down_sync(0xffffffffu, a2, off);
            a3 += __shfl_down_sync(0xffffffffu, a3, off);
        }
        if (lane < 4) {
            float* dst = &g_ybar[b * D_INNER + h * 16 + lane * 4];
            atomicAdd(dst + 0, a0); atomicAdd(dst + 1, a1);
            atomicAdd(dst + 2, a2); atomicAdd(dst + 3, a3);
        }
        __syncwarp();
    }
}

// ---------------- K5: B1 — per-segment final state + decay product (from S/d summaries) ----------------
__global__ __launch_bounds__(128) void k_B1() {
    const int w = threadIdx.x >> 5, lane = threadIdx.x & 31;
    const int gw = blockIdx.x * 4 + w;
    const int b = gw >> 9, h = (gw >> 4) & 31, seg = gw & 15;
    const int bh = b * NHEADS + h;
    const size_t base = (size_t)(bh * NC + seg * CPS) * 128 + lane * 4;
    const float* dptr = &g_d[bh * NC + seg * CPS];
    float h0 = 0.f, h1 = 0.f, h2 = 0.f, h3 = 0.f, dp = 1.f;
    #pragma unroll 4
    for (int cc = 0; cc < CPS; cc++) {
        ushort4 us = *reinterpret_cast<const ushort4*>(&g_S[base + (size_t)cc * 128]);
        float d = dptr[cc];
        h0 = h0 * d + bf_dec(us.x); h1 = h1 * d + bf_dec(us.y);
        h2 = h2 * d + bf_dec(us.z); h3 = h3 * d + bf_dec(us.w);
        dp *= d;
    }
    *reinterpret_cast<float4*>(&g_Sfin[(size_t)(bh * NSEG + seg) * 128 + lane * 4]) =
        make_float4(h0, h1, h2, h3);
    if (lane == 0) g_Dseg[bh * NSEG + seg] = dp;
}

// ---------------- K6: combine segment states ----------------
__global__ void k_combine() {
    int tid = blockIdx.x * 128 + threadIdx.x;   // 65536 threads
    int bh = tid >> 7, pn = tid & 127;
    float H = 0.f;
    #pragma unroll
    for (int s = 0; s < NSEG; s++) {
        g_hin[(size_t)(bh * NSEG + s) * 128 + pn] = H;
        if (s < NSEG - 1)
            H = H * g_Dseg[bh * NSEG + s] + g_Sfin[(size_t)(bh * NSEG + s) * 128 + pn];
    }
}

// ---------------- K7: B3 — replay segments: acc += h . G, h = h*d + S ----------------
__global__ __launch_bounds__(128) void k_B3() {
    const int w = threadIdx.x >> 5, lane = threadIdx.x & 31;
    const int gw = blockIdx.x * 4 + w;
    const int b = gw >> 9, h = (gw >> 4) & 31, seg = gw & 15;
    const int bh = b * NHEADS + h;
    float4 hv = *reinterpret_cast<const float4*>(&g_hin[(size_t)(bh * NSEG + seg) * 128 + lane * 4]);
    float h0 = hv.x, h1 = hv.y, h2 = hv.z, h3 = hv.w;
    float accP = 0.f;
    const size_t base = (size_t)(bh * NC + seg * CPS) * 128 + lane * 4;
    const float* dptr = &g_d[bh * NC + seg * CPS];
    #pragma unroll 2
    for (int cc = 0; cc < CPS; cc++) {
        ushort4 uS = *reinterpret_cast<const ushort4*>(&g_S[base + (size_t)cc * 128]);
        ushort4 uG = *reinterpret_cast<const ushort4*>(&g_G[base + (size_t)cc * 128]);
        float d = dptr[cc];
        accP += h0 * bf_dec(uG.x) + h1 * bf_dec(uG.y) + h2 * bf_dec(uG.z) + h3 * bf_dec(uG.w);
        h0 = h0 * d + bf_dec(uS.x); h1 = h1 * d + bf_dec(uS.y);
        h2 = h2 * d + bf_dec(uS.z); h3 = h3 * d + bf_dec(uS.w);
    }
    accP += __shfl_xor_sync(0xffffffffu, accP, 1);
    if (!(lane & 1)) atomicAdd(&g_ybar[b * D_INNER + h * 16 + (lane >> 1)], accP);
}

// ---------------- K8: pooled = (ybar/L) @ W_out^T; logits = pooled @ W_cls^T + b_cls ----------------
__global__ void k_final(const float* __restrict__ Wout, const float* __restrict__ Wcls,
                        const float* __restrict__ bcls, float* __restrict__ out) {
    __shared__ float sp[D_MODEL];
    const int b = blockIdx.x, m = threadIdx.x;
    float s = 0.f;
    #pragma unroll 8
    for (int d = 0; d < D_INNER; d++) s += g_ybar[b * D_INNER + d] * Wout[m * D_INNER + d];
    sp[m] = s * (1.f / SEQLEN);
    __syncthreads();
    if (m < OUT_SIZE) {
        float r = bcls[m];
        #pragma unroll 8
        for (int k = 0; k < D_MODEL; k++) r += Wcls[m * D_MODEL + k] * sp[k];
        out[b * OUT_SIZE + m] = r;
    }
}

// ---------------- launch ----------------
extern "C" void kernel_launch(void* const* d_in, const int* in_sizes, int n_in,
                              void* d_out, int out_size) {
    const float* x    = (const float*)d_in[0];
    const float* Win  = (const float*)d_in[1];
    const float* bin  = (const float*)d_in[2];
    const float* Wip  = (const float*)d_in[3];
    const float* cw   = (const float*)d_in[4];
    const float* cb   = (const float*)d_in[5];
    const float* dtb  = (const float*)d_in[6];
    const float* Alog = (const float*)d_in[7];
    const float* Dp   = (const float*)d_in[8];
    const float* Wout = (const float*)d_in[9];
    const float* Wcls = (const float*)d_in[10];
    const float* bcls = (const float*)d_in[11];
    float* out = (float*)d_out;

    k_wcomb<<<243, 256>>>(Wip, Win, bin);
    dim3 g2(NTOK / BM, (D_INPROJ + BN - 1) / BN);        // 512 x 17
    k_gemm<<<g2, 256>>>(x);
    k_zero<<<BATCH, D_INNER>>>();
    k_passA<<<BATCH * NC, 256>>>(cw, cb, dtb, Alog, Dp); // 8192 blocks
    k_B1<<<(BATCH * NHEADS * NSEG) / 4, 128>>>();
    k_combine<<<512, 128>>>();
    k_B3<<<(BATCH * NHEADS * NSEG) / 4, 128>>>();
    k_final<<<BATCH, D_MODEL>>>(Wout, Wcls, bcls, out);
}